// round 15
// baseline (speedup 1.0000x reference)
#include <cuda_runtime.h>
#include <cuda_bf16.h>
#include <cstdint>

#define N_NODES 50000
#define N_EDGES 800000
#define D_IN    96
#define D_EDGE  32
#define D_OUT   96
#define D_FEAT  128
#define N_TYPES 4

typedef unsigned long long ull;

// ---------------- PTX helpers ----------------
__device__ __forceinline__ uint32_t smem_to_u32(const void* p) {
    uint32_t a;
    asm("{ .reg .u64 t; cvta.to.shared.u64 t, %1; cvt.u32.u64 %0, t; }"
        : "=r"(a) : "l"(p));
    return a;
}
#define CPASYNC16(saddr, gptr) \
    asm volatile("cp.async.ca.shared.global [%0], [%1], 16;" \
                 :: "r"(saddr), "l"(gptr) : "memory")
#define CPASYNC_COMMIT() asm volatile("cp.async.commit_group;" ::: "memory")
#define CPASYNC_WAIT0()  asm volatile("cp.async.wait_group 0;" ::: "memory")
// r = {lo16 = bf16(a), hi16 = bf16(b)}
#define CVT_BF16X2_F32(result, a, b) \
    asm("cvt.rn.satfinite.bf16x2.f32 %0, %1, %2;" : "=r"(result) : "f"(b), "f"(a))
#define LDMX4(r, addr) \
    asm volatile("ldmatrix.sync.aligned.m8n8.x4.shared.b16 {%0,%1,%2,%3}, [%4];" \
                 : "=r"((r)[0]), "=r"((r)[1]), "=r"((r)[2]), "=r"((r)[3]) : "r"(addr))
#define MMA_BF16(d, a, b0_, b1_) \
    asm volatile("mma.sync.aligned.m16n8k16.row.col.f32.bf16.bf16.f32 " \
                 "{%0,%1,%2,%3},{%4,%5,%6,%7},{%8,%9},{%0,%1,%2,%3};" \
                 : "+f"((d)[0]), "+f"((d)[1]), "+f"((d)[2]), "+f"((d)[3]) \
                 : "r"((a)[0]), "r"((a)[1]), "r"((a)[2]), "r"((a)[3]), \
                   "r"(b0_), "r"(b1_))

// ---------------- scratch ----------------
#define FEAT_ELEMS ((size_t)N_TYPES * N_NODES * D_FEAT)
#define CNT_OFFSET FEAT_ELEMS
__device__ __align__(16) float g_scratch[FEAT_ELEMS + (size_t)N_TYPES * N_NODES + 16];

// W pre-split (0.25-scaled) bf16 hi/lo in [t][{hi,lo}][c=96][k=136] layout
#define WSTRIDE 136
__device__ __align__(16) __nv_bfloat16 g_wprep[(size_t)N_TYPES * 2 * 96 * WSTRIDE];

// ---------------------------------------------------------------------------
// Prep: W[t][k][c] * 0.25 -> bf16 hi + lo residual, stored [c][k] stride 136.
// ---------------------------------------------------------------------------
__global__ __launch_bounds__(256) void prep_kernel(const float* __restrict__ W)
{
    int i = blockIdx.x * blockDim.x + threadIdx.x;
    if (i >= N_TYPES * D_FEAT * D_OUT) return;
    int t = i / (D_FEAT * D_OUT);
    int r = i - t * (D_FEAT * D_OUT);
    int k = r / D_OUT, c = r - k * D_OUT;

    float w = 0.25f * W[i];
    __nv_bfloat16 hi = __float2bfloat16(w);
    __nv_bfloat16 lo = __float2bfloat16(w - __bfloat162float(hi));

    size_t base = (size_t)t * 2 * 96 * WSTRIDE;
    g_wprep[base + (size_t)c * WSTRIDE + k]        = hi;
    g_wprep[base + (size_t)(96 + c) * WSTRIDE + k] = lo;
}

// ---------------------------------------------------------------------------
// Kernel 1: edge scatter (scalar-atomic version, measured fastest).
// ---------------------------------------------------------------------------
#define SC_BATCH 4

__global__ __launch_bounds__(256) void scatter_kernel(
    const float* __restrict__ x, const float* __restrict__ ef,
    const int* __restrict__ src, const int* __restrict__ dst,
    const int* __restrict__ et)
{
    const int lane = threadIdx.x & 31;
    const int gw   = (blockIdx.x * blockDim.x + threadIdx.x) >> 5;
    const int nw   = (gridDim.x * blockDim.x) >> 5;

    float* cnt = g_scratch + CNT_OFFSET;

    for (long e0 = (long)gw * SC_BATCH; e0 < N_EDGES; e0 += (long)nw * SC_BATCH) {
        int  s[SC_BATCH], d[SC_BATCH], t[SC_BATCH];
        bool v[SC_BATCH];
#pragma unroll
        for (int i = 0; i < SC_BATCH; i++) {
            long e = e0 + i;
            v[i] = (e < N_EDGES);
            long ec = v[i] ? e : 0;
            s[i] = __ldg(&src[ec]); d[i] = __ldg(&dst[ec]); t[i] = __ldg(&et[ec]);
        }
#pragma unroll
        for (int i = 0; i < SC_BATCH; i++) {
            if (!v[i]) continue;
            const float* xr = x + (size_t)s[i] * D_IN;
            float x0 = xr[lane], x1 = xr[lane + 32], x2 = xr[lane + 64];
            float ea = ef[(size_t)s[i] * D_EDGE + lane];
            float eb = ef[(size_t)d[i] * D_EDGE + lane];
            float ev = fabsf(ea - eb);
            float* row = g_scratch + ((size_t)t[i] * N_NODES + d[i]) * D_FEAT;
            atomicAdd(row + lane,      x0);
            atomicAdd(row + lane + 32, x1);
            atomicAdd(row + lane + 64, x2);
            atomicAdd(row + lane + 96, ev);
            if (lane == 0)
                atomicAdd(&cnt[(size_t)t[i] * N_NODES + d[i]], 1.0f);
        }
    }
}

// ---------------------------------------------------------------------------
// Kernel 2: bf16 3-term split GEMM via ldmatrix + mma.sync (sm_80 PTX).
// One CTA per 128-node tile, 8 warps; warp w owns rows 16w..16w+15, all 96
// cols (12 n8 tiles, 48 fp32 acc). Types and split terms accumulate in regs.
// ---------------------------------------------------------------------------
#define ASTRIDE 136
#define SM_BIAS 0                          // 384 floats
#define SM_A_HI 1536
#define SM_A_LO (SM_A_HI + 128 * ASTRIDE * 2)   // 36352
#define SM_B_HI (SM_A_LO + 128 * ASTRIDE * 2)   // 71168
#define SM_B_LO (SM_B_HI + 96 * ASTRIDE * 2)    // 97280
#define MMA_SMEM_BYTES (SM_B_LO + 96 * ASTRIDE * 2)  // 123392
#define B_CHUNKS (96 * ASTRIDE * 2 / 16)   // 1632

__global__ __launch_bounds__(256) void mma_gemm_kernel(
    const float* __restrict__ bias,    // [4, 96]
    float* __restrict__ out)           // [N, 96]
{
    extern __shared__ __align__(16) unsigned char smem[];
    const uint32_t sb = smem_to_u32(smem);
    const int tid  = threadIdx.x;
    const int wid  = tid >> 5;
    const int lane = tid & 31;
    const int node0 = blockIdx.x * 128;

    // bias -> smem, 0.25-scaled. GRID-STRIDE: covers all 384 entries with
    // 256 threads (the R8/R14 bug was a `tid < 384` guard filling only 256).
    for (int i = tid; i < N_TYPES * D_OUT; i += 256)
        ((float*)smem)[i] = 0.25f * bias[i];

    // ldmatrix per-lane address offsets (bytes)
    const int selA = lane >> 3;           // 0..3: m-lo/k-lo, m-hi/k-lo, m-lo/k-hi, m-hi/k-hi
    const uint32_t a_off = (uint32_t)((wid * 16 + (selA & 1) * 8 + (lane & 7)) * (ASTRIDE * 2)
                                      + (selA >> 1) * 16);
    // B tiles: n-lo/k-lo, n-lo/k-hi, n-hi/k-lo, n-hi/k-hi
    const uint32_t b_off = (uint32_t)((((lane >> 4) & 1) * 8 + (lane & 7)) * (ASTRIDE * 2)
                                      + ((lane >> 3) & 1) * 16);

    float acc[12][4];
#pragma unroll
    for (int q = 0; q < 12; q++)
#pragma unroll
        for (int c = 0; c < 4; c++) acc[q][c] = 0.0f;

    for (int t = 0; t < N_TYPES; t++) {
        __syncthreads();   // previous type's smem reads done (also covers bias fill)

        // ---- B hi/lo via cp.async (layout already matches smem)
        {
            const char* wp = (const char*)(g_wprep + (size_t)t * 2 * 96 * WSTRIDE);
#pragma unroll
            for (int q = 0; q < 7; q++) {
                int id = q * 256 + tid;
                if (id < B_CHUNKS) {
                    CPASYNC16(sb + SM_B_HI + id * 16, wp + id * 16);
                    CPASYNC16(sb + SM_B_LO + id * 16, wp + 96 * ASTRIDE * 2 + id * 16);
                }
            }
            CPASYNC_COMMIT();
        }

        // ---- A tile: feat fp32 -> bf16 hi/lo (raw values; 0.25 folded in W)
        const float* ft = g_scratch + (size_t)t * N_NODES * D_FEAT;
        for (int i2 = tid; i2 < 128 * 64; i2 += 256) {
            int row = i2 >> 6, kp = i2 & 63;
            int n = node0 + row;
            float2 v = make_float2(0.0f, 0.0f);
            if (n < N_NODES)
                v = *reinterpret_cast<const float2*>(ft + (size_t)n * D_FEAT + 2 * kp);
            uint32_t hi2; CVT_BF16X2_F32(hi2, v.x, v.y);
            __nv_bfloat162 h2 = *reinterpret_cast<__nv_bfloat162*>(&hi2);
            float rx = v.x - __bfloat162float(h2.x);
            float ry = v.y - __bfloat162float(h2.y);
            uint32_t lo2; CVT_BF16X2_F32(lo2, rx, ry);
            uint32_t off = (uint32_t)(row * (ASTRIDE * 2) + kp * 4);
            *reinterpret_cast<uint32_t*>(smem + SM_A_HI + off) = hi2;
            *reinterpret_cast<uint32_t*>(smem + SM_A_LO + off) = lo2;
        }
        CPASYNC_WAIT0();
        __syncthreads();

        // ---- 8 k16 steps x (A_hi*B_hi + A_lo*B_hi + A_hi*B_lo)
#pragma unroll
        for (int j = 0; j < 8; j++) {
            const uint32_t kb = 32u * j;
            uint32_t ah[4], al[4];
            LDMX4(ah, sb + SM_A_HI + a_off + kb);
            LDMX4(al, sb + SM_A_LO + a_off + kb);
#pragma unroll
            for (int p = 0; p < 6; p++) {
                uint32_t boff = b_off + (uint32_t)(p * 16 * ASTRIDE * 2) + kb;
                uint32_t bh[4], bl[4];
                LDMX4(bh, sb + SM_B_HI + boff);
                MMA_BF16(acc[2 * p],     ah, bh[0], bh[1]);
                MMA_BF16(acc[2 * p + 1], ah, bh[2], bh[3]);
                MMA_BF16(acc[2 * p],     al, bh[0], bh[1]);
                MMA_BF16(acc[2 * p + 1], al, bh[2], bh[3]);
                LDMX4(bl, sb + SM_B_LO + boff);
                MMA_BF16(acc[2 * p],     ah, bl[0], bl[1]);
                MMA_BF16(acc[2 * p + 1], ah, bl[2], bl[3]);
            }
        }
    }

    // ---- epilogue: D frag rows g, g+8; add cnt * 0.25*bias; float2 stores
    {
        const int g  = lane >> 2;
        const int tq = lane & 3;
        const float* cnt = g_scratch + CNT_OFFSET;
        const float* bsm = (const float*)smem;   // [4][96], 0.25-scaled
#pragma unroll
        for (int half = 0; half < 2; half++) {
            int row = node0 + wid * 16 + g + 8 * half;
            if (row >= N_NODES) continue;
            float c0 = cnt[row];
            float c1 = cnt[(size_t)N_NODES + row];
            float c2 = cnt[2 * (size_t)N_NODES + row];
            float c3 = cnt[3 * (size_t)N_NODES + row];
            float* op = out + (size_t)row * D_OUT;
#pragma unroll
            for (int q = 0; q < 12; q++) {
                int col = 8 * q + 2 * tq;
                float b0 = c0 * bsm[col]       + c1 * bsm[96 + col]
                         + c2 * bsm[192 + col] + c3 * bsm[288 + col];
                float b1 = c0 * bsm[col + 1]       + c1 * bsm[96 + col + 1]
                         + c2 * bsm[192 + col + 1] + c3 * bsm[288 + col + 1];
                float2 o;
                o.x = acc[q][2 * half]     + b0;
                o.y = acc[q][2 * half + 1] + b1;
                *reinterpret_cast<float2*>(op + col) = o;
            }
        }
    }
}

// ---------------------------------------------------------------------------
extern "C" void kernel_launch(void* const* d_in, const int* in_sizes, int n_in,
                              void* d_out, int out_size)
{
    const float* x   = (const float*)d_in[0];
    const float* ef  = (const float*)d_in[1];
    const int*   ei  = (const int*)  d_in[2];
    const int*   et  = (const int*)  d_in[3];
    const float* W   = (const float*)d_in[4];
    const float* b   = (const float*)d_in[5];
    float*       out = (float*)d_out;

    const int* srcp = ei;
    const int* dstp = ei + N_EDGES;

    void* scratch_ptr = nullptr;
    cudaGetSymbolAddress(&scratch_ptr, g_scratch);
    cudaMemsetAsync(scratch_ptr, 0, sizeof(g_scratch), 0);

    prep_kernel<<<(N_TYPES * D_FEAT * D_OUT + 255) / 256, 256>>>(W);
    scatter_kernel<<<592, 256>>>(x, ef, srcp, dstp, et);

    static int smem_set = 0;
    if (!smem_set) {
        cudaFuncSetAttribute(mma_gemm_kernel,
                             cudaFuncAttributeMaxDynamicSharedMemorySize,
                             MMA_SMEM_BYTES);
        smem_set = 1;
    }
    mma_gemm_kernel<<<(N_NODES + 127) / 128, 256, MMA_SMEM_BYTES>>>(b, out);
}

// round 16
// speedup vs baseline: 1.5662x; 1.5662x over previous
#include <cuda_runtime.h>
#include <cuda_bf16.h>
#include <cstdint>

#define N_NODES 50000
#define N_EDGES 800000
#define D_IN    96
#define D_EDGE  32
#define D_OUT   96
#define D_FEAT  128
#define N_TYPES 4

typedef unsigned long long ull;

// ---------------- PTX helpers ----------------
__device__ __forceinline__ uint32_t smem_to_u32(const void* p) {
    uint32_t a;
    asm("{ .reg .u64 t; cvta.to.shared.u64 t, %1; cvt.u32.u64 %0, t; }"
        : "=r"(a) : "l"(p));
    return a;
}
#define CPASYNC16(saddr, gptr) \
    asm volatile("cp.async.ca.shared.global [%0], [%1], 16;" \
                 :: "r"(saddr), "l"(gptr) : "memory")
#define CPASYNC_COMMIT() asm volatile("cp.async.commit_group;" ::: "memory")
#define CPASYNC_WAIT0()  asm volatile("cp.async.wait_group 0;" ::: "memory")
// r = {lo16 = bf16(a), hi16 = bf16(b)}
#define CVT_BF16X2_F32(result, a, b) \
    asm("cvt.rn.satfinite.bf16x2.f32 %0, %1, %2;" : "=r"(result) : "f"(b), "f"(a))
#define LDMX4(r, addr) \
    asm volatile("ldmatrix.sync.aligned.m8n8.x4.shared.b16 {%0,%1,%2,%3}, [%4];" \
                 : "=r"((r)[0]), "=r"((r)[1]), "=r"((r)[2]), "=r"((r)[3]) : "r"(addr))
#define MMA_BF16(d, a, b0_, b1_) \
    asm volatile("mma.sync.aligned.m16n8k16.row.col.f32.bf16.bf16.f32 " \
                 "{%0,%1,%2,%3},{%4,%5,%6,%7},{%8,%9},{%0,%1,%2,%3};" \
                 : "+f"((d)[0]), "+f"((d)[1]), "+f"((d)[2]), "+f"((d)[3]) \
                 : "r"((a)[0]), "r"((a)[1]), "r"((a)[2]), "r"((a)[3]), \
                   "r"(b0_), "r"(b1_))

// ---------------- scratch ----------------
#define FEAT_ELEMS ((size_t)N_TYPES * N_NODES * D_FEAT)
#define CNT_OFFSET FEAT_ELEMS
__device__ __align__(16) float g_scratch[FEAT_ELEMS + (size_t)N_TYPES * N_NODES + 16];

// W pre-split (0.25-scaled) bf16 hi/lo in [t][{hi,lo}][c=96][k=136] layout
#define WSTRIDE 136
__device__ __align__(16) __nv_bfloat16 g_wprep[(size_t)N_TYPES * 2 * 96 * WSTRIDE];

// ---------------------------------------------------------------------------
// Prep: W[t][k][c] * 0.25 -> bf16 hi + lo residual, stored [c][k] stride 136.
// ---------------------------------------------------------------------------
__global__ __launch_bounds__(256) void prep_kernel(const float* __restrict__ W)
{
    int i = blockIdx.x * blockDim.x + threadIdx.x;
    if (i >= N_TYPES * D_FEAT * D_OUT) return;
    int t = i / (D_FEAT * D_OUT);
    int r = i - t * (D_FEAT * D_OUT);
    int k = r / D_OUT, c = r - k * D_OUT;

    float w = 0.25f * W[i];
    __nv_bfloat16 hi = __float2bfloat16(w);
    __nv_bfloat16 lo = __float2bfloat16(w - __bfloat162float(hi));

    size_t base = (size_t)t * 2 * 96 * WSTRIDE;
    g_wprep[base + (size_t)c * WSTRIDE + k]        = hi;
    g_wprep[base + (size_t)(96 + c) * WSTRIDE + k] = lo;
}

// ---------------------------------------------------------------------------
// Kernel 1: edge scatter (scalar-atomic version, measured fastest).
// ---------------------------------------------------------------------------
#define SC_BATCH 4

__global__ __launch_bounds__(256) void scatter_kernel(
    const float* __restrict__ x, const float* __restrict__ ef,
    const int* __restrict__ src, const int* __restrict__ dst,
    const int* __restrict__ et)
{
    const int lane = threadIdx.x & 31;
    const int gw   = (blockIdx.x * blockDim.x + threadIdx.x) >> 5;
    const int nw   = (gridDim.x * blockDim.x) >> 5;

    float* cnt = g_scratch + CNT_OFFSET;

    for (long e0 = (long)gw * SC_BATCH; e0 < N_EDGES; e0 += (long)nw * SC_BATCH) {
        int  s[SC_BATCH], d[SC_BATCH], t[SC_BATCH];
        bool v[SC_BATCH];
#pragma unroll
        for (int i = 0; i < SC_BATCH; i++) {
            long e = e0 + i;
            v[i] = (e < N_EDGES);
            long ec = v[i] ? e : 0;
            s[i] = __ldg(&src[ec]); d[i] = __ldg(&dst[ec]); t[i] = __ldg(&et[ec]);
        }
#pragma unroll
        for (int i = 0; i < SC_BATCH; i++) {
            if (!v[i]) continue;
            const float* xr = x + (size_t)s[i] * D_IN;
            float x0 = xr[lane], x1 = xr[lane + 32], x2 = xr[lane + 64];
            float ea = ef[(size_t)s[i] * D_EDGE + lane];
            float eb = ef[(size_t)d[i] * D_EDGE + lane];
            float ev = fabsf(ea - eb);
            float* row = g_scratch + ((size_t)t[i] * N_NODES + d[i]) * D_FEAT;
            atomicAdd(row + lane,      x0);
            atomicAdd(row + lane + 32, x1);
            atomicAdd(row + lane + 64, x2);
            atomicAdd(row + lane + 96, ev);
            if (lane == 0)
                atomicAdd(&cnt[(size_t)t[i] * N_NODES + d[i]], 1.0f);
        }
    }
}

// ---------------------------------------------------------------------------
// Kernel 2: bf16 3-term split GEMM via ldmatrix + mma.sync.
// TILE_N=64 nodes per CTA, 8 warps: warps 0-3 = row blocks x cols 0-47,
// warps 4-7 = same row blocks x cols 48-95 (each: 16 rows x 6 n8 tiles,
// 24 acc regs). smem 88.6 KB -> 2 CTAs/SM so one CTA's MMA hides the
// other's fill latency (R15 ran 1 CTA/SM fully serialized).
// ---------------------------------------------------------------------------
#define TILE_N  64
#define ASTRIDE 136
#define SM_BIAS 0                              // 384 floats = 1536 B
#define SM_A_HI 1536                           // 64*272 = 17408
#define SM_A_LO (SM_A_HI + TILE_N * ASTRIDE * 2)     // 18944
#define SM_B_HI (SM_A_LO + TILE_N * ASTRIDE * 2)     // 36352
#define SM_B_LO (SM_B_HI + 96 * ASTRIDE * 2)         // 62464
#define MMA_SMEM_BYTES (SM_B_LO + 96 * ASTRIDE * 2)  // 88576
#define B_CHUNKS (96 * ASTRIDE * 2 / 16)       // 1632

__global__ __launch_bounds__(256) void mma_gemm_kernel(
    const float* __restrict__ bias,    // [4, 96]
    float* __restrict__ out)           // [N, 96]
{
    extern __shared__ __align__(16) unsigned char smem[];
    const uint32_t sb = smem_to_u32(smem);
    const int tid  = threadIdx.x;
    const int wid  = tid >> 5;
    const int lane = tid & 31;
    const int node0 = blockIdx.x * TILE_N;
    const int rblk  = wid & 3;                 // row block 0..3 (16 rows each)
    const int cbase = (wid >> 2) * 48;         // column half: 0 or 48

    // bias -> smem, 0.25-scaled (grid-stride: all 384 entries)
    for (int i = tid; i < N_TYPES * D_OUT; i += 256)
        ((float*)smem)[i] = 0.25f * bias[i];

    // ldmatrix per-lane address offsets (bytes) — layout validated in R15
    const int selA = lane >> 3;
    const uint32_t a_off = (uint32_t)((rblk * 16 + (selA & 1) * 8 + (lane & 7)) * (ASTRIDE * 2)
                                      + (selA >> 1) * 16);
    const uint32_t b_off = (uint32_t)(((cbase + ((lane >> 4) & 1) * 8 + (lane & 7))) * (ASTRIDE * 2)
                                      + ((lane >> 3) & 1) * 16);

    float acc[6][4];
#pragma unroll
    for (int q = 0; q < 6; q++)
#pragma unroll
        for (int c = 0; c < 4; c++) acc[q][c] = 0.0f;

    for (int t = 0; t < N_TYPES; t++) {
        __syncthreads();   // previous type's smem reads done (also covers bias fill)

        // ---- B hi/lo via cp.async (layout already matches smem)
        {
            const char* wp = (const char*)(g_wprep + (size_t)t * 2 * 96 * WSTRIDE);
#pragma unroll
            for (int q = 0; q < 7; q++) {
                int id = q * 256 + tid;
                if (id < B_CHUNKS) {
                    CPASYNC16(sb + SM_B_HI + id * 16, wp + id * 16);
                    CPASYNC16(sb + SM_B_LO + id * 16, wp + 96 * ASTRIDE * 2 + id * 16);
                }
            }
            CPASYNC_COMMIT();
        }

        // ---- A tile: feat fp32 -> bf16 hi/lo (raw values; 0.25 folded in W)
        const float* ft = g_scratch + (size_t)t * N_NODES * D_FEAT;
        for (int i2 = tid; i2 < TILE_N * 64; i2 += 256) {
            int row = i2 >> 6, kp = i2 & 63;
            int n = node0 + row;
            float2 v = make_float2(0.0f, 0.0f);
            if (n < N_NODES)
                v = *reinterpret_cast<const float2*>(ft + (size_t)n * D_FEAT + 2 * kp);
            uint32_t hi2; CVT_BF16X2_F32(hi2, v.x, v.y);
            __nv_bfloat162 h2 = *reinterpret_cast<__nv_bfloat162*>(&hi2);
            float rx = v.x - __bfloat162float(h2.x);
            float ry = v.y - __bfloat162float(h2.y);
            uint32_t lo2; CVT_BF16X2_F32(lo2, rx, ry);
            uint32_t off = (uint32_t)(row * (ASTRIDE * 2) + kp * 4);
            *reinterpret_cast<uint32_t*>(smem + SM_A_HI + off) = hi2;
            *reinterpret_cast<uint32_t*>(smem + SM_A_LO + off) = lo2;
        }
        CPASYNC_WAIT0();
        __syncthreads();

        // ---- 8 k16 steps x (A_hi*B_hi + A_lo*B_hi + A_hi*B_lo)
#pragma unroll
        for (int j = 0; j < 8; j++) {
            const uint32_t kb = 32u * j;
            uint32_t ah[4], al[4];
            LDMX4(ah, sb + SM_A_HI + a_off + kb);
            LDMX4(al, sb + SM_A_LO + a_off + kb);
#pragma unroll
            for (int p = 0; p < 3; p++) {
                uint32_t boff = b_off + (uint32_t)(p * 16 * ASTRIDE * 2) + kb;
                uint32_t bh[4], bl[4];
                LDMX4(bh, sb + SM_B_HI + boff);
                MMA_BF16(acc[2 * p],     ah, bh[0], bh[1]);
                MMA_BF16(acc[2 * p + 1], ah, bh[2], bh[3]);
                MMA_BF16(acc[2 * p],     al, bh[0], bh[1]);
                MMA_BF16(acc[2 * p + 1], al, bh[2], bh[3]);
                LDMX4(bl, sb + SM_B_LO + boff);
                MMA_BF16(acc[2 * p],     ah, bl[0], bl[1]);
                MMA_BF16(acc[2 * p + 1], ah, bl[2], bl[3]);
            }
        }
    }

    // ---- epilogue: D frag rows g, g+8; add cnt * 0.25*bias; float2 stores
    {
        const int g  = lane >> 2;
        const int tq = lane & 3;
        const float* cnt = g_scratch + CNT_OFFSET;
        const float* bsm = (const float*)smem;   // [4][96], 0.25-scaled
#pragma unroll
        for (int half = 0; half < 2; half++) {
            int row = node0 + rblk * 16 + g + 8 * half;
            if (row >= N_NODES) continue;
            float c0 = cnt[row];
            float c1 = cnt[(size_t)N_NODES + row];
            float c2 = cnt[2 * (size_t)N_NODES + row];
            float c3 = cnt[3 * (size_t)N_NODES + row];
            float* op = out + (size_t)row * D_OUT;
#pragma unroll
            for (int q = 0; q < 6; q++) {
                int col = cbase + 8 * q + 2 * tq;
                float b0 = c0 * bsm[col]       + c1 * bsm[96 + col]
                         + c2 * bsm[192 + col] + c3 * bsm[288 + col];
                float b1 = c0 * bsm[col + 1]       + c1 * bsm[96 + col + 1]
                         + c2 * bsm[192 + col + 1] + c3 * bsm[288 + col + 1];
                float2 o;
                o.x = acc[q][2 * half]     + b0;
                o.y = acc[q][2 * half + 1] + b1;
                *reinterpret_cast<float2*>(op + col) = o;
            }
        }
    }
}

// ---------------------------------------------------------------------------
extern "C" void kernel_launch(void* const* d_in, const int* in_sizes, int n_in,
                              void* d_out, int out_size)
{
    const float* x   = (const float*)d_in[0];
    const float* ef  = (const float*)d_in[1];
    const int*   ei  = (const int*)  d_in[2];
    const int*   et  = (const int*)  d_in[3];
    const float* W   = (const float*)d_in[4];
    const float* b   = (const float*)d_in[5];
    float*       out = (float*)d_out;

    const int* srcp = ei;
    const int* dstp = ei + N_EDGES;

    void* scratch_ptr = nullptr;
    cudaGetSymbolAddress(&scratch_ptr, g_scratch);
    cudaMemsetAsync(scratch_ptr, 0, sizeof(g_scratch), 0);

    prep_kernel<<<(N_TYPES * D_FEAT * D_OUT + 255) / 256, 256>>>(W);
    scatter_kernel<<<592, 256>>>(x, ef, srcp, dstp, et);

    static int smem_set = 0;
    if (!smem_set) {
        cudaFuncSetAttribute(mma_gemm_kernel,
                             cudaFuncAttributeMaxDynamicSharedMemorySize,
                             MMA_SMEM_BYTES);
        smem_set = 1;
    }
    mma_gemm_kernel<<<(N_NODES + TILE_N - 1) / TILE_N, 256, MMA_SMEM_BYTES>>>(b, out);
}

// round 17
// speedup vs baseline: 1.7705x; 1.1305x over previous
#include <cuda_runtime.h>
#include <cuda_bf16.h>
#include <cstdint>

#define N_NODES 50000
#define N_EDGES 800000
#define D_IN    96
#define D_EDGE  32
#define D_OUT   96
#define D_FEAT  128
#define N_TYPES 4

typedef unsigned long long ull;

// ---------------- PTX helpers ----------------
__device__ __forceinline__ uint32_t smem_to_u32(const void* p) {
    uint32_t a;
    asm("{ .reg .u64 t; cvta.to.shared.u64 t, %1; cvt.u32.u64 %0, t; }"
        : "=r"(a) : "l"(p));
    return a;
}
#define CPASYNC16(saddr, gptr) \
    asm volatile("cp.async.ca.shared.global [%0], [%1], 16;" \
                 :: "r"(saddr), "l"(gptr) : "memory")
#define CPASYNC_COMMIT() asm volatile("cp.async.commit_group;" ::: "memory")
#define CPASYNC_WAIT0()  asm volatile("cp.async.wait_group 0;" ::: "memory")
// r = {lo16 = bf16(a), hi16 = bf16(b)}
#define CVT_BF16X2_F32(result, a, b) \
    asm("cvt.rn.satfinite.bf16x2.f32 %0, %1, %2;" : "=r"(result) : "f"(b), "f"(a))
#define LDMX4(r, addr) \
    asm volatile("ldmatrix.sync.aligned.m8n8.x4.shared.b16 {%0,%1,%2,%3}, [%4];" \
                 : "=r"((r)[0]), "=r"((r)[1]), "=r"((r)[2]), "=r"((r)[3]) : "r"(addr))
#define MMA_BF16(d, a, b0_, b1_) \
    asm volatile("mma.sync.aligned.m16n8k16.row.col.f32.bf16.bf16.f32 " \
                 "{%0,%1,%2,%3},{%4,%5,%6,%7},{%8,%9},{%0,%1,%2,%3};" \
                 : "+f"((d)[0]), "+f"((d)[1]), "+f"((d)[2]), "+f"((d)[3]) \
                 : "r"((a)[0]), "r"((a)[1]), "r"((a)[2]), "r"((a)[3]), \
                   "r"(b0_), "r"(b1_))

// ---------------- scratch ----------------
#define FEAT_ELEMS ((size_t)N_TYPES * N_NODES * D_FEAT)
#define CNT_OFFSET FEAT_ELEMS
__device__ __align__(16) float g_scratch[FEAT_ELEMS + (size_t)N_TYPES * N_NODES + 16];

// W pre-split (0.25-scaled) bf16 hi/lo in [t][{hi,lo}][c=96][k=136] layout
#define WSTRIDE 136
__device__ __align__(16) __nv_bfloat16 g_wprep[(size_t)N_TYPES * 2 * 96 * WSTRIDE];

// ---------------------------------------------------------------------------
// Prep: W[t][k][c] * 0.25 -> bf16 hi + lo residual, stored [c][k] stride 136.
// ---------------------------------------------------------------------------
__global__ __launch_bounds__(256) void prep_kernel(const float* __restrict__ W)
{
    int i = blockIdx.x * blockDim.x + threadIdx.x;
    if (i >= N_TYPES * D_FEAT * D_OUT) return;
    int t = i / (D_FEAT * D_OUT);
    int r = i - t * (D_FEAT * D_OUT);
    int k = r / D_OUT, c = r - k * D_OUT;

    float w = 0.25f * W[i];
    __nv_bfloat16 hi = __float2bfloat16(w);
    __nv_bfloat16 lo = __float2bfloat16(w - __bfloat162float(hi));

    size_t base = (size_t)t * 2 * 96 * WSTRIDE;
    g_wprep[base + (size_t)c * WSTRIDE + k]        = hi;
    g_wprep[base + (size_t)(96 + c) * WSTRIDE + k] = lo;
}

// ---------------------------------------------------------------------------
// Kernel 1: edge scatter (scalar-atomic version, measured fastest).
// ---------------------------------------------------------------------------
#define SC_BATCH 4

__global__ __launch_bounds__(256) void scatter_kernel(
    const float* __restrict__ x, const float* __restrict__ ef,
    const int* __restrict__ src, const int* __restrict__ dst,
    const int* __restrict__ et)
{
    const int lane = threadIdx.x & 31;
    const int gw   = (blockIdx.x * blockDim.x + threadIdx.x) >> 5;
    const int nw   = (gridDim.x * blockDim.x) >> 5;

    float* cnt = g_scratch + CNT_OFFSET;

    for (long e0 = (long)gw * SC_BATCH; e0 < N_EDGES; e0 += (long)nw * SC_BATCH) {
        int  s[SC_BATCH], d[SC_BATCH], t[SC_BATCH];
        bool v[SC_BATCH];
#pragma unroll
        for (int i = 0; i < SC_BATCH; i++) {
            long e = e0 + i;
            v[i] = (e < N_EDGES);
            long ec = v[i] ? e : 0;
            s[i] = __ldg(&src[ec]); d[i] = __ldg(&dst[ec]); t[i] = __ldg(&et[ec]);
        }
#pragma unroll
        for (int i = 0; i < SC_BATCH; i++) {
            if (!v[i]) continue;
            const float* xr = x + (size_t)s[i] * D_IN;
            float x0 = xr[lane], x1 = xr[lane + 32], x2 = xr[lane + 64];
            float ea = ef[(size_t)s[i] * D_EDGE + lane];
            float eb = ef[(size_t)d[i] * D_EDGE + lane];
            float ev = fabsf(ea - eb);
            float* row = g_scratch + ((size_t)t[i] * N_NODES + d[i]) * D_FEAT;
            atomicAdd(row + lane,      x0);
            atomicAdd(row + lane + 32, x1);
            atomicAdd(row + lane + 64, x2);
            atomicAdd(row + lane + 96, ev);
            if (lane == 0)
                atomicAdd(&cnt[(size_t)t[i] * N_NODES + d[i]], 1.0f);
        }
    }
}

// ---------------------------------------------------------------------------
// Kernel 2: bf16 3-term split GEMM via ldmatrix + mma.sync.
// TILE_N=64, 8 warps (4 row blocks x 2 column halves), 2 CTAs/SM.
// A fill uses TRUNCATING split: hi = top-16-bits (one PRMT per float pair),
// lo = exact residual CVT'd once. float4 loads + STS.64 stores.
// ---------------------------------------------------------------------------
#define TILE_N  64
#define ASTRIDE 136
#define SM_BIAS 0                              // 384 floats = 1536 B
#define SM_A_HI 1536                           // 64*272 = 17408
#define SM_A_LO (SM_A_HI + TILE_N * ASTRIDE * 2)     // 18944
#define SM_B_HI (SM_A_LO + TILE_N * ASTRIDE * 2)     // 36352
#define SM_B_LO (SM_B_HI + 96 * ASTRIDE * 2)         // 62464
#define MMA_SMEM_BYTES (SM_B_LO + 96 * ASTRIDE * 2)  // 88576
#define B_CHUNKS (96 * ASTRIDE * 2 / 16)       // 1632

__global__ __launch_bounds__(256) void mma_gemm_kernel(
    const float* __restrict__ bias,    // [4, 96]
    float* __restrict__ out)           // [N, 96]
{
    extern __shared__ __align__(16) unsigned char smem[];
    const uint32_t sb = smem_to_u32(smem);
    const int tid  = threadIdx.x;
    const int wid  = tid >> 5;
    const int lane = tid & 31;
    const int node0 = blockIdx.x * TILE_N;
    const int rblk  = wid & 3;                 // row block 0..3 (16 rows each)
    const int cbase = (wid >> 2) * 48;         // column half: 0 or 48

    // bias -> smem, 0.25-scaled (grid-stride: all 384 entries)
    for (int i = tid; i < N_TYPES * D_OUT; i += 256)
        ((float*)smem)[i] = 0.25f * bias[i];

    // ldmatrix per-lane address offsets (bytes) — layout validated in R15/16
    const int selA = lane >> 3;
    const uint32_t a_off = (uint32_t)((rblk * 16 + (selA & 1) * 8 + (lane & 7)) * (ASTRIDE * 2)
                                      + (selA >> 1) * 16);
    const uint32_t b_off = (uint32_t)(((cbase + ((lane >> 4) & 1) * 8 + (lane & 7))) * (ASTRIDE * 2)
                                      + ((lane >> 3) & 1) * 16);

    float acc[6][4];
#pragma unroll
    for (int q = 0; q < 6; q++)
#pragma unroll
        for (int c = 0; c < 4; c++) acc[q][c] = 0.0f;

    for (int t = 0; t < N_TYPES; t++) {
        __syncthreads();   // previous type's smem reads done (also covers bias fill)

        // ---- B hi/lo via cp.async (layout already matches smem)
        {
            const char* wp = (const char*)(g_wprep + (size_t)t * 2 * 96 * WSTRIDE);
#pragma unroll
            for (int q = 0; q < 7; q++) {
                int id = q * 256 + tid;
                if (id < B_CHUNKS) {
                    CPASYNC16(sb + SM_B_HI + id * 16, wp + id * 16);
                    CPASYNC16(sb + SM_B_LO + id * 16, wp + 96 * ASTRIDE * 2 + id * 16);
                }
            }
            CPASYNC_COMMIT();
        }

        // ---- A tile: feat fp32 -> bf16 hi(trunc)/lo(residual), float4 loads
        const float* ft = g_scratch + (size_t)t * N_NODES * D_FEAT;
        for (int i4 = tid; i4 < TILE_N * 32; i4 += 256) {
            int row = i4 >> 5;                 // node within tile
            int kq  = i4 & 31;                 // group of 4 k values
            int n = node0 + row;
            uint32_t hiA = 0, hiB = 0, loA = 0, loB = 0;
            if (n < N_NODES) {
                float4 v = *reinterpret_cast<const float4*>(
                               ft + (size_t)n * D_FEAT + 4 * kq);
                uint32_t ux = __float_as_uint(v.x), uy = __float_as_uint(v.y);
                uint32_t uz = __float_as_uint(v.z), uw = __float_as_uint(v.w);
                hiA = __byte_perm(ux, uy, 0x7632);   // {bf16t(v.x), bf16t(v.y)}
                hiB = __byte_perm(uz, uw, 0x7632);
                float rx = v.x - __uint_as_float(ux & 0xFFFF0000u);
                float ry = v.y - __uint_as_float(uy & 0xFFFF0000u);
                float rz = v.z - __uint_as_float(uz & 0xFFFF0000u);
                float rw = v.w - __uint_as_float(uw & 0xFFFF0000u);
                CVT_BF16X2_F32(loA, rx, ry);
                CVT_BF16X2_F32(loB, rz, rw);
            }
            uint32_t off = (uint32_t)(row * (ASTRIDE * 2) + kq * 8);
            *reinterpret_cast<uint2*>(smem + SM_A_HI + off) = make_uint2(hiA, hiB);
            *reinterpret_cast<uint2*>(smem + SM_A_LO + off) = make_uint2(loA, loB);
        }
        CPASYNC_WAIT0();
        __syncthreads();

        // ---- 8 k16 steps x (A_hi*B_hi + A_lo*B_hi + A_hi*B_lo)
#pragma unroll
        for (int j = 0; j < 8; j++) {
            const uint32_t kb = 32u * j;
            uint32_t ah[4], al[4];
            LDMX4(ah, sb + SM_A_HI + a_off + kb);
            LDMX4(al, sb + SM_A_LO + a_off + kb);
#pragma unroll
            for (int p = 0; p < 3; p++) {
                uint32_t boff = b_off + (uint32_t)(p * 16 * ASTRIDE * 2) + kb;
                uint32_t bh[4], bl[4];
                LDMX4(bh, sb + SM_B_HI + boff);
                MMA_BF16(acc[2 * p],     ah, bh[0], bh[1]);
                MMA_BF16(acc[2 * p + 1], ah, bh[2], bh[3]);
                MMA_BF16(acc[2 * p],     al, bh[0], bh[1]);
                MMA_BF16(acc[2 * p + 1], al, bh[2], bh[3]);
                LDMX4(bl, sb + SM_B_LO + boff);
                MMA_BF16(acc[2 * p],     ah, bl[0], bl[1]);
                MMA_BF16(acc[2 * p + 1], ah, bl[2], bl[3]);
            }
        }
    }

    // ---- epilogue: D frag rows g, g+8; add cnt * 0.25*bias; float2 stores
    {
        const int g  = lane >> 2;
        const int tq = lane & 3;
        const float* cnt = g_scratch + CNT_OFFSET;
        const float* bsm = (const float*)smem;   // [4][96], 0.25-scaled
#pragma unroll
        for (int half = 0; half < 2; half++) {
            int row = node0 + rblk * 16 + g + 8 * half;
            if (row >= N_NODES) continue;
            float c0 = cnt[row];
            float c1 = cnt[(size_t)N_NODES + row];
            float c2 = cnt[2 * (size_t)N_NODES + row];
            float c3 = cnt[3 * (size_t)N_NODES + row];
            float* op = out + (size_t)row * D_OUT;
#pragma unroll
            for (int q = 0; q < 6; q++) {
                int col = cbase + 8 * q + 2 * tq;
                float b0 = c0 * bsm[col]       + c1 * bsm[96 + col]
                         + c2 * bsm[192 + col] + c3 * bsm[288 + col];
                float b1 = c0 * bsm[col + 1]       + c1 * bsm[96 + col + 1]
                         + c2 * bsm[192 + col + 1] + c3 * bsm[288 + col + 1];
                float2 o;
                o.x = acc[q][2 * half]     + b0;
                o.y = acc[q][2 * half + 1] + b1;
                *reinterpret_cast<float2*>(op + col) = o;
            }
        }
    }
}

// ---------------------------------------------------------------------------
extern "C" void kernel_launch(void* const* d_in, const int* in_sizes, int n_in,
                              void* d_out, int out_size)
{
    const float* x   = (const float*)d_in[0];
    const float* ef  = (const float*)d_in[1];
    const int*   ei  = (const int*)  d_in[2];
    const int*   et  = (const int*)  d_in[3];
    const float* W   = (const float*)d_in[4];
    const float* b   = (const float*)d_in[5];
    float*       out = (float*)d_out;

    const int* srcp = ei;
    const int* dstp = ei + N_EDGES;

    void* scratch_ptr = nullptr;
    cudaGetSymbolAddress(&scratch_ptr, g_scratch);
    cudaMemsetAsync(scratch_ptr, 0, sizeof(g_scratch), 0);

    prep_kernel<<<(N_TYPES * D_FEAT * D_OUT + 255) / 256, 256>>>(W);
    scatter_kernel<<<592, 256>>>(x, ef, srcp, dstp, et);

    static int smem_set = 0;
    if (!smem_set) {
        cudaFuncSetAttribute(mma_gemm_kernel,
                             cudaFuncAttributeMaxDynamicSharedMemorySize,
                             MMA_SMEM_BYTES);
        smem_set = 1;
    }
    mma_gemm_kernel<<<(N_NODES + TILE_N - 1) / TILE_N, 256, MMA_SMEM_BYTES>>>(b, out);
}